// round 16
// baseline (speedup 1.0000x reference)
#include <cuda_runtime.h>
#include <cstdint>

#define T_SEQ 4096
#define E_DIM 300
#define H_DIM 256
#define A_DIM 150
#define G_DIM 1325
#define LCL 8

// ---------------- scratch (static device arrays; no allocation) ----------------
__device__ float g_emb[T_SEQ * E_DIM];
__device__ float g_xp[T_SEQ * 2048];
__device__ float g_h[T_SEQ * 512];
__device__ float g_l1[T_SEQ * A_DIM];
__device__ float g_l2[T_SEQ * A_DIM];
__device__ float g_logits[T_SEQ];
__device__ float g_Hs[T_SEQ * A_DIM];
__device__ float g_He[T_SEQ * A_DIM];
__device__ float g_Ep[T_SEQ * A_DIM];

// ---------------- helpers ----------------
__device__ __forceinline__ float sigmoidf_fast(float x) {
    return __fdividef(1.0f, 1.0f + __expf(-x));
}
__device__ __forceinline__ float tanhf_fast(float x) {
    float e = __expf(-2.0f * x);
    return __fdividef(1.0f - e, 1.0f + e);
}
__device__ __forceinline__ uint32_t smem_u32(const void* p) {
    return (uint32_t)__cvta_generic_to_shared(p);
}

// ---------------- embedding gather ----------------
__global__ void embed_kernel(const int* __restrict__ tok, const float* __restrict__ table) {
    int idx = blockIdx.x * blockDim.x + threadIdx.x;
    if (idx >= T_SEQ * E_DIM) return;
    int t = idx / E_DIM;
    int e = idx - t * E_DIM;
    g_emb[idx] = table[(long)tok[t] * E_DIM + e];
}

// ---------------- big tiled SGEMM: 128x128 block, 8x8 micro (xp projection) ----------------
__global__ __launch_bounds__(256) void gemm128_kernel(
    const float* __restrict__ A, const float* __restrict__ B,
    const float* __restrict__ bias, float* __restrict__ C,
    int M, int N, int K, int lda, int ldb, int ldc)
{
    __shared__ float As[16][128];
    __shared__ float Bs[16][128];
    int m0 = blockIdx.y * 128, n0 = blockIdx.x * 128;
    int tid = threadIdx.x;
    int tx = tid & 15, ty = tid >> 4;
    float acc[8][8];
#pragma unroll
    for (int i = 0; i < 8; i++)
#pragma unroll
        for (int j = 0; j < 8; j++) acc[i][j] = 0.0f;

    for (int k0 = 0; k0 < K; k0 += 16) {
#pragma unroll
        for (int u = 0; u < 8; u++) {
            int i = tid + u * 256;
            int m = i >> 4, k = i & 15;
            float v = 0.0f;
            if (m0 + m < M && k0 + k < K) v = A[(long)(m0 + m) * lda + k0 + k];
            As[k][m] = v;
        }
#pragma unroll
        for (int u = 0; u < 8; u++) {
            int i = tid + u * 256;
            int n = i >> 4, k = i & 15;
            float v = 0.0f;
            if (n0 + n < N && k0 + k < K) v = B[(long)(n0 + n) * ldb + k0 + k];
            Bs[k][n] = v;
        }
        __syncthreads();
#pragma unroll
        for (int k = 0; k < 16; k++) {
            float a[8], b[8];
#pragma unroll
            for (int i = 0; i < 8; i++) a[i] = As[k][ty * 8 + i];
#pragma unroll
            for (int j = 0; j < 8; j++) b[j] = Bs[k][tx * 8 + j];
#pragma unroll
            for (int i = 0; i < 8; i++)
#pragma unroll
                for (int j = 0; j < 8; j++) acc[i][j] = fmaf(a[i], b[j], acc[i][j]);
        }
        __syncthreads();
    }
#pragma unroll
    for (int i = 0; i < 8; i++) {
        int m = m0 + ty * 8 + i;
        if (m >= M) continue;
#pragma unroll
        for (int j = 0; j < 8; j++) {
            int n = n0 + tx * 8 + j;
            if (n >= N) continue;
            float v = acc[i][j];
            if (bias) v += bias[n];
            C[(long)m * ldc + n] = v;
        }
    }
}

// ---------------- skinny SGEMM: 64x64 block, 4x4 micro (N~150 cases) ----------------
// grid (3, 64) = 192 CTAs for M=4096, N=150: full-chip occupancy vs 96 CTAs
// of the 128-wide tile (measured 60us at issue=24.8% with 52 idle SMs).
#define BM 64
#define BN 64
#define BK 16
__global__ __launch_bounds__(256) void gemm_kernel(
    const float* __restrict__ A, const float* __restrict__ B,
    const float* __restrict__ bias, float* __restrict__ C,
    int M, int N, int K, int lda, int ldb, int ldc, int b_off, int relu)
{
    __shared__ float As[BK][BM];
    __shared__ float Bs[BK][BN];
    int m0 = blockIdx.y * BM, n0 = blockIdx.x * BN;
    int tid = threadIdx.x;
    int tx = tid & 15, ty = tid >> 4;
    float acc[4][4];
#pragma unroll
    for (int i = 0; i < 4; i++)
#pragma unroll
        for (int j = 0; j < 4; j++) acc[i][j] = 0.0f;

    for (int k0 = 0; k0 < K; k0 += BK) {
#pragma unroll
        for (int u = 0; u < 4; u++) {
            int i = tid + u * 256;
            int m = i >> 4, k = i & 15;
            float v = 0.0f;
            if (m0 + m < M && k0 + k < K) v = A[(long)(m0 + m) * lda + k0 + k];
            As[k][m] = v;
        }
#pragma unroll
        for (int u = 0; u < 4; u++) {
            int i = tid + u * 256;
            int n = i >> 4, k = i & 15;
            float v = 0.0f;
            if (n0 + n < N && k0 + k < K) v = B[(long)(n0 + n) * ldb + b_off + k0 + k];
            Bs[k][n] = v;
        }
        __syncthreads();
#pragma unroll
        for (int k = 0; k < BK; k++) {
            float a[4], b[4];
#pragma unroll
            for (int i = 0; i < 4; i++) a[i] = As[k][ty * 4 + i];
#pragma unroll
            for (int j = 0; j < 4; j++) b[j] = Bs[k][tx * 4 + j];
#pragma unroll
            for (int i = 0; i < 4; i++)
#pragma unroll
                for (int j = 0; j < 4; j++) acc[i][j] = fmaf(a[i], b[j], acc[i][j]);
        }
        __syncthreads();
    }
#pragma unroll
    for (int i = 0; i < 4; i++) {
        int m = m0 + ty * 4 + i;
        if (m >= M) continue;
#pragma unroll
        for (int j = 0; j < 4; j++) {
            int n = n0 + tx * 4 + j;
            if (n >= N) continue;
            float v = acc[i][j];
            if (bias) v += bias[n];
            if (relu) v = fmaxf(v, 0.0f);
            C[(long)m * ldc + n] = v;
        }
    }
}

// ---------------- BiLSTM recurrence (byte-identical to R9, the measured best) ----------------
__global__ void __cluster_dims__(8, 1, 1) __launch_bounds__(256, 1)
lstm_kernel(const float* __restrict__ Whh_f, const float* __restrict__ Whh_b,
            const float* __restrict__ xp, float* __restrict__ h_out)
{
    __shared__ __align__(16) float hb[4][256];
    __shared__ __align__(16) unsigned long long bar[4];

    int tid = threadIdx.x;
    int dir = blockIdx.x >> 3;
    unsigned r;
    asm("mov.u32 %0, %%cluster_ctarank;" : "=r"(r));

    int h_local = tid >> 3;
    int gate = (tid >> 1) & 3;
    int half = tid & 1;
    int row = gate * 256 + (int)r * 32 + h_local;

    const unsigned long long* Wq = (const unsigned long long*)
        ((dir == 0 ? Whh_f : Whh_b) + (long)row * 256 + half * 128);
    unsigned long long wq[64];
#pragma unroll
    for (int k = 0; k < 64; k++) wq[k] = Wq[k];

    hb[0][tid] = 0.0f;
    hb[1][tid] = 0.0f;
    hb[2][tid] = 0.0f;
    hb[3][tid] = 0.0f;

    uint32_t barAddr = smem_u32(&bar[0]);
    uint32_t hbAddr  = smem_u32(&hb[0][0]);
    if (tid == 0) {
#pragma unroll
        for (int i = 0; i < 4; i++) {
            asm volatile("mbarrier.init.shared.b64 [%0], 1;" :: "r"(barAddr + i * 8) : "memory");
            asm volatile("mbarrier.arrive.expect_tx.shared.b64 _, [%0], 1024;" :: "r"(barAddr + i * 8) : "memory");
        }
    }
    __syncthreads();
    asm volatile("barrier.cluster.arrive.aligned;" ::: "memory");
    asm volatile("barrier.cluster.wait.aligned;" ::: "memory");

    uint32_t peerHb[LCL], peerBar[LCL];
#pragma unroll
    for (int pe = 0; pe < LCL; pe++) {
        asm("mapa.shared::cluster.u32 %0, %1, %2;" : "=r"(peerHb[pe])  : "r"(hbAddr),  "r"(pe));
        asm("mapa.shared::cluster.u32 %0, %1, %2;" : "=r"(peerBar[pe]) : "r"(barAddr), "r"(pe));
    }

    float c = 0.0f;
    int lane = tid & 31, gbase = lane & ~7;
    const int xcol = dir * 1024 + row;
    int t = (dir == 0) ? 0 : (T_SEQ - 1);
    int dt = (dir == 0) ? 1 : -1;
    int slot = (int)r * 32 + h_local;
    bool isProd = ((tid & 7) == 0);
    float xv = __ldg(&xp[(long)t * 2048 + xcol]);

    for (int step = 0; step < T_SEQ; step++) {
        int p = step & 3;
        if (step) {
            uint32_t mb = barAddr + p * 8;
            int par = ((step - 1) >> 2) & 1;
            asm volatile(
                "{\n\t.reg .pred P;\n"
                "WL%=:\n\t"
                "mbarrier.try_wait.parity.acquire.cta.shared::cta.b64 P, [%0], %1, 0x989680;\n\t"
                "@P bra WD%=;\n\t"
                "bra WL%=;\n"
                "WD%=:\n\t}"
                :: "r"(mb), "r"(par) : "memory");
            if (tid == 0)
                asm volatile("mbarrier.arrive.expect_tx.shared.b64 _, [%0], 1024;" :: "r"(mb) : "memory");
        }
        int tn = t + dt;
        float xnext = (step < T_SEQ - 1) ? __ldg(&xp[(long)tn * 2048 + xcol]) : 0.0f;

        const ulonglong2* h2p = (const ulonglong2*)(&hb[p][half * 128]);
        unsigned long long a0 = 0ull, a1 = 0ull, a2 = 0ull, a3 = 0ull;
#pragma unroll
        for (int k = 0; k < 16; k++) {
            ulonglong2 v0 = h2p[2 * k];
            ulonglong2 v1 = h2p[2 * k + 1];
            asm("fma.rn.f32x2 %0, %1, %2, %0;" : "+l"(a0) : "l"(wq[4 * k + 0]), "l"(v0.x));
            asm("fma.rn.f32x2 %0, %1, %2, %0;" : "+l"(a1) : "l"(wq[4 * k + 1]), "l"(v0.y));
            asm("fma.rn.f32x2 %0, %1, %2, %0;" : "+l"(a2) : "l"(wq[4 * k + 2]), "l"(v1.x));
            asm("fma.rn.f32x2 %0, %1, %2, %0;" : "+l"(a3) : "l"(wq[4 * k + 3]), "l"(v1.y));
        }
        float acc = ((__uint_as_float((unsigned)a0) + __uint_as_float((unsigned)(a0 >> 32)))
                   + (__uint_as_float((unsigned)a1) + __uint_as_float((unsigned)(a1 >> 32))))
                  + ((__uint_as_float((unsigned)a2) + __uint_as_float((unsigned)(a2 >> 32)))
                   + (__uint_as_float((unsigned)a3) + __uint_as_float((unsigned)(a3 >> 32))));
        acc += __shfl_xor_sync(0xffffffffu, acc, 1);
        float z = acc + xv;

        float zi = __shfl_sync(0xffffffffu, z, gbase + 0);
        float zf = __shfl_sync(0xffffffffu, z, gbase + 2);
        float zg = __shfl_sync(0xffffffffu, z, gbase + 4);
        float zo = __shfl_sync(0xffffffffu, z, gbase + 6);

        float ig = sigmoidf_fast(zi);
        float fg = sigmoidf_fast(zf);
        float og = sigmoidf_fast(zo);
        float gg = tanhf_fast(zg);
        c = fg * c + ig * gg;
        float hv = og * tanhf_fast(c);

        if (isProd) {
            h_out[(long)t * 512 + dir * 256 + slot] = hv;
            if (step < T_SEQ - 1) {
                int np = (step + 1) & 3;
                uint32_t doff = (uint32_t)(np * 1024 + slot * 4);
                uint32_t boff = (uint32_t)(np * 8);
#pragma unroll
                for (int pe = 0; pe < LCL; pe++) {
                    uint32_t dst = peerHb[pe] + doff;
                    uint32_t mb  = peerBar[pe] + boff;
                    asm volatile(
                        "st.async.shared::cluster.mbarrier::complete_tx::bytes.f32 [%0], %1, [%2];"
                        :: "r"(dst), "f"(hv), "r"(mb) : "memory");
                }
            }
        }
        xv = xnext;
        t = tn;
    }
    asm volatile("barrier.cluster.arrive.aligned;" ::: "memory");
    asm volatile("barrier.cluster.wait.aligned;" ::: "memory");
}

// ---------------- final 150->1 dot for attention logits ----------------
__global__ void logits_dot_kernel(const float* __restrict__ L2, const float* __restrict__ aw3,
                                  const float* __restrict__ ab3, float* __restrict__ logits) {
    int t = blockIdx.x * 8 + (threadIdx.x >> 5);
    int lane = threadIdx.x & 31;
    if (t >= T_SEQ) return;
    float s = 0.0f;
    for (int o = lane; o < A_DIM; o += 32) s += L2[(long)t * A_DIM + o] * aw3[o];
#pragma unroll
    for (int d = 16; d > 0; d >>= 1) s += __shfl_down_sync(0xffffffffu, s, d);
    if (lane == 0) logits[t] = s + ab3[0];
}

// ---------------- fused span kernel ----------------
__global__ __launch_bounds__(256) void span_kernel(
    const float* __restrict__ logits,
    const float* __restrict__ Hs, const float* __restrict__ He, const float* __restrict__ Ep,
    const float* __restrict__ sw1, const float* __restrict__ sb1,
    const float* __restrict__ sw2, const float* __restrict__ sb2,
    const float* __restrict__ sw3, const float* __restrict__ sb3,
    float* __restrict__ out)
{
    __shared__ float attn_s[32][12];
    __shared__ float x1s[32 * 153];
    __shared__ float x2s[150 * 33];
    __shared__ float swn_s[152];
    __shared__ float sb1_s[152];
    __shared__ float sb2_s[152];
    __shared__ float sw3_s[152];

    int b = blockIdx.x;
    int n = b / 128 + 1;
    int w0 = (b % 128) * 32;
    int Wn = T_SEQ + 1 - n;
    int off = (n - 1) * (T_SEQ + 1) - (n - 1) * n / 2;
    int tid = threadIdx.x;

    for (int o = tid; o < A_DIM; o += 256) {
        swn_s[o] = sw1[(long)o * G_DIM + (G_DIM - 1)];
        sb1_s[o] = sb1[o];
        sb2_s[o] = sb2[o];
        sw3_s[o] = sw3[o];
    }
    if (tid < 32) {
        int w = w0 + tid;
        if (w < Wn) {
            float m = -1e30f;
            for (int j = 0; j < n; j++) m = fmaxf(m, logits[w + j]);
            float e[10];
            float s = 0.0f;
            for (int j = 0; j < n; j++) { e[j] = __expf(logits[w + j] - m); s += e[j]; }
            float inv = __fdividef(1.0f, s);
            for (int j = 0; j < n; j++) attn_s[tid][j] = e[j] * inv;
        }
    }
    __syncthreads();

    for (int p = tid; p < 32 * A_DIM; p += 256) {
        int i = p / A_DIM, o = p - i * A_DIM;
        int w = w0 + i;
        float v = 0.0f;
        if (w < Wn) {
            float z = Hs[(long)w * A_DIM + o] + He[(long)(w + n - 1) * A_DIM + o]
                    + (float)n * swn_s[o] + sb1_s[o];
            for (int j = 0; j < n; j++)
                z = fmaf(attn_s[i][j], Ep[(long)(w + j) * A_DIM + o], z);
            v = fmaxf(z, 0.0f);
        }
        x1s[i * 153 + o] = v;
    }
    __syncthreads();

    for (int p = tid; p < A_DIM * 32; p += 256) {
        int i = p & 31;
        int o2 = p >> 5;
        const float* w2 = sw2 + (long)o2 * A_DIM;
        float z = sb2_s[o2];
#pragma unroll 5
        for (int k = 0; k < A_DIM; k++) z = fmaf(x1s[i * 153 + k], __ldg(&w2[k]), z);
        x2s[o2 * 33 + i] = fmaxf(z, 0.0f);
    }
    __syncthreads();

    {
        int i = tid >> 3;
        int cpart = tid & 7;
        float s = 0.0f;
        for (int o2 = cpart; o2 < A_DIM; o2 += 8) s = fmaf(x2s[o2 * 33 + i], sw3_s[o2], s);
        s += __shfl_down_sync(0xffffffffu, s, 4, 8);
        s += __shfl_down_sync(0xffffffffu, s, 2, 8);
        s += __shfl_down_sync(0xffffffffu, s, 1, 8);
        if (cpart == 0) {
            int w = w0 + i;
            if (w < Wn) out[off + w] = s + sb3[0];
        }
    }
}

// ---------------- launch: 3-stream fork/join (graph-capturable) ----------------
extern "C" void kernel_launch(void* const* d_in, const int* in_sizes, int n_in,
                              void* d_out, int out_size) {
    const int*   tok    = (const int*)  d_in[0];
    const float* table  = (const float*)d_in[1];
    const float* W_ih_f = (const float*)d_in[2];
    const float* W_hh_f = (const float*)d_in[3];
    const float* b_f    = (const float*)d_in[4];
    const float* W_ih_b = (const float*)d_in[5];
    const float* W_hh_b = (const float*)d_in[6];
    const float* b_b    = (const float*)d_in[7];
    const float* aw1    = (const float*)d_in[8];
    const float* ab1    = (const float*)d_in[9];
    const float* aw2    = (const float*)d_in[10];
    const float* ab2    = (const float*)d_in[11];
    const float* aw3    = (const float*)d_in[12];
    const float* ab3    = (const float*)d_in[13];
    const float* sw1    = (const float*)d_in[14];
    const float* sb1    = (const float*)d_in[15];
    const float* sw2    = (const float*)d_in[16];
    const float* sb2    = (const float*)d_in[17];
    const float* sw3    = (const float*)d_in[18];
    const float* sb3    = (const float*)d_in[19];
    float* out = (float*)d_out;

    void *p;
    float *emb, *xp, *h, *l1, *l2, *lg, *hs, *he, *ep;
    cudaGetSymbolAddress(&p, g_emb);    emb = (float*)p;
    cudaGetSymbolAddress(&p, g_xp);     xp  = (float*)p;
    cudaGetSymbolAddress(&p, g_h);      h   = (float*)p;
    cudaGetSymbolAddress(&p, g_l1);     l1  = (float*)p;
    cudaGetSymbolAddress(&p, g_l2);     l2  = (float*)p;
    cudaGetSymbolAddress(&p, g_logits); lg  = (float*)p;
    cudaGetSymbolAddress(&p, g_Hs);     hs  = (float*)p;
    cudaGetSymbolAddress(&p, g_He);     he  = (float*)p;
    cudaGetSymbolAddress(&p, g_Ep);     ep  = (float*)p;

    static cudaStream_t s1 = 0, s2 = 0;
    static cudaEvent_t evA = 0, evB = 0, evC = 0, evD = 0, evE = 0;
    if (!s1) {
        cudaStreamCreateWithFlags(&s1, cudaStreamNonBlocking);
        cudaStreamCreateWithFlags(&s2, cudaStreamNonBlocking);
        cudaEventCreateWithFlags(&evA, cudaEventDisableTiming);
        cudaEventCreateWithFlags(&evB, cudaEventDisableTiming);
        cudaEventCreateWithFlags(&evC, cudaEventDisableTiming);
        cudaEventCreateWithFlags(&evD, cudaEventDisableTiming);
        cudaEventCreateWithFlags(&evE, cudaEventDisableTiming);
    }

    // embed on main stream
    embed_kernel<<<(T_SEQ * E_DIM + 255) / 256, 256>>>(tok, table);
    cudaEventRecord(evA, 0);

    // fork: xp_b on s1, Ep on s2 (both need only emb); xp_f on main
    cudaStreamWaitEvent(s1, evA, 0);
    cudaStreamWaitEvent(s2, evA, 0);
    gemm128_kernel<<<dim3(8, 32), 256, 0, 0 >>>(emb, W_ih_f, b_f, xp,        T_SEQ, 1024, E_DIM, E_DIM, E_DIM, 2048);
    gemm128_kernel<<<dim3(8, 32), 256, 0, s1>>>(emb, W_ih_b, b_b, xp + 1024, T_SEQ, 1024, E_DIM, E_DIM, E_DIM, 2048);
    gemm_kernel  <<<dim3(3, 64), 256, 0, s2>>>(emb, sw1, (const float*)0, ep, T_SEQ, A_DIM, E_DIM, E_DIM, G_DIM, A_DIM, 1024, 0);
    cudaEventRecord(evB, s1);
    cudaEventRecord(evE, s2);

    // lstm needs both xp halves
    cudaStreamWaitEvent(0, evB, 0);
    lstm_kernel<<<16, 256>>>(W_hh_f, W_hh_b, xp, h);
    cudaEventRecord(evC, 0);

    // fork after lstm: attention-logit chain on s1, Hs/He on main
    cudaStreamWaitEvent(s1, evC, 0);
    gemm_kernel<<<dim3(3, 64), 256, 0, s1>>>(h,  aw1, ab1, l1, T_SEQ, A_DIM, 512,   512,   512,   A_DIM, 0, 1);
    gemm_kernel<<<dim3(3, 64), 256, 0, s1>>>(l1, aw2, ab2, l2, T_SEQ, A_DIM, A_DIM, A_DIM, A_DIM, A_DIM, 0, 1);
    logits_dot_kernel<<<T_SEQ / 8, 256, 0, s1>>>(l2, aw3, ab3, lg);
    cudaEventRecord(evD, s1);

    gemm_kernel<<<dim3(3, 64), 256, 0, 0>>>(h, sw1, (const float*)0, hs, T_SEQ, A_DIM, 512, 512, G_DIM, A_DIM, 0,   0);
    gemm_kernel<<<dim3(3, 64), 256, 0, 0>>>(h, sw1, (const float*)0, he, T_SEQ, A_DIM, 512, 512, G_DIM, A_DIM, 512, 0);

    // join all branches, then span
    cudaStreamWaitEvent(0, evD, 0);
    cudaStreamWaitEvent(0, evE, 0);
    span_kernel<<<1280, 256>>>(lg, hs, he, ep, sw1, sb1, sw2, sb2, sw3, sb3, out);
}

// round 17
// speedup vs baseline: 1.0137x; 1.0137x over previous
#include <cuda_runtime.h>
#include <cstdint>

#define T_SEQ 4096
#define E_DIM 300
#define H_DIM 256
#define A_DIM 150
#define G_DIM 1325
#define LCL 8

// ---------------- scratch (static device arrays; no allocation) ----------------
__device__ float g_xp[T_SEQ * 2048];
__device__ float g_h[T_SEQ * 512];
__device__ float g_l1[T_SEQ * A_DIM];
__device__ float g_l2[T_SEQ * A_DIM];
__device__ float g_logits[T_SEQ];
__device__ float g_Hs[T_SEQ * A_DIM];
__device__ float g_He[T_SEQ * A_DIM];
__device__ float g_Ep[T_SEQ * A_DIM];

// ---------------- helpers ----------------
__device__ __forceinline__ float sigmoidf_fast(float x) {
    return __fdividef(1.0f, 1.0f + __expf(-x));
}
__device__ __forceinline__ float tanhf_fast(float x) {
    float e = __expf(-2.0f * x);
    return __fdividef(1.0f - e, 1.0f + e);
}
__device__ __forceinline__ uint32_t smem_u32(const void* p) {
    return (uint32_t)__cvta_generic_to_shared(p);
}

// ---------------- big tiled SGEMM with fused embedding gather ----------------
// C[M,N] = emb[M,K] @ B[N,K]^T (+bias), where emb[m][k] = table[tok[m]][k].
// 128x128 block, 8x8 micro, 256 threads. Used for the xp projections.
__global__ __launch_bounds__(256) void gemm128_kernel(
    const int* __restrict__ tok, const float* __restrict__ table,
    const float* __restrict__ B,
    const float* __restrict__ bias, float* __restrict__ C,
    int M, int N, int K, int ldb, int ldc)
{
    __shared__ float As[16][128];
    __shared__ float Bs[16][128];
    int m0 = blockIdx.y * 128, n0 = blockIdx.x * 128;
    int tid = threadIdx.x;
    int tx = tid & 15, ty = tid >> 4;
    float acc[8][8];
#pragma unroll
    for (int i = 0; i < 8; i++)
#pragma unroll
        for (int j = 0; j < 8; j++) acc[i][j] = 0.0f;

    for (int k0 = 0; k0 < K; k0 += 16) {
#pragma unroll
        for (int u = 0; u < 8; u++) {
            int i = tid + u * 256;
            int m = i >> 4, k = i & 15;
            float v = 0.0f;
            if (m0 + m < M && k0 + k < K)
                v = table[(long)tok[m0 + m] * E_DIM + k0 + k];
            As[k][m] = v;
        }
#pragma unroll
        for (int u = 0; u < 8; u++) {
            int i = tid + u * 256;
            int n = i >> 4, k = i & 15;
            float v = 0.0f;
            if (n0 + n < N && k0 + k < K) v = B[(long)(n0 + n) * ldb + k0 + k];
            Bs[k][n] = v;
        }
        __syncthreads();
#pragma unroll
        for (int k = 0; k < 16; k++) {
            float a[8], b[8];
#pragma unroll
            for (int i = 0; i < 8; i++) a[i] = As[k][ty * 8 + i];
#pragma unroll
            for (int j = 0; j < 8; j++) b[j] = Bs[k][tx * 8 + j];
#pragma unroll
            for (int i = 0; i < 8; i++)
#pragma unroll
                for (int j = 0; j < 8; j++) acc[i][j] = fmaf(a[i], b[j], acc[i][j]);
        }
        __syncthreads();
    }
#pragma unroll
    for (int i = 0; i < 8; i++) {
        int m = m0 + ty * 8 + i;
        if (m >= M) continue;
#pragma unroll
        for (int j = 0; j < 8; j++) {
            int n = n0 + tx * 8 + j;
            if (n >= N) continue;
            float v = acc[i][j];
            if (bias) v += bias[n];
            C[(long)m * ldc + n] = v;
        }
    }
}

// ---------------- skinny SGEMM: 32x64 block, 4x4 micro, 128 threads ----------------
// grid (3, 128) = 384 CTAs for M=4096, N=150 -> 2-3 CTAs per SM so barrier/LDS
// latency of one CTA is covered by another (R16 measured occ=16.6%, issue=25%
// at one 256-thread CTA/SM). Optional tok: A row m = table-gather (Ep GEMM).
#define BM 32
#define BN 64
#define BK 16
__global__ __launch_bounds__(128) void gemm_kernel(
    const int* __restrict__ tok,
    const float* __restrict__ A, const float* __restrict__ B,
    const float* __restrict__ bias, float* __restrict__ C,
    int M, int N, int K, int lda, int ldb, int ldc, int b_off, int relu)
{
    __shared__ float As[BK][BM];
    __shared__ float Bs[BK][BN];
    int m0 = blockIdx.y * BM, n0 = blockIdx.x * BN;
    int tid = threadIdx.x;
    int tx = tid & 15, ty = tid >> 4;
    float acc[4][4];
#pragma unroll
    for (int i = 0; i < 4; i++)
#pragma unroll
        for (int j = 0; j < 4; j++) acc[i][j] = 0.0f;

    for (int k0 = 0; k0 < K; k0 += BK) {
#pragma unroll
        for (int u = 0; u < 4; u++) {
            int i = tid + u * 128;
            int m = i >> 4, k = i & 15;
            float v = 0.0f;
            if (m0 + m < M && k0 + k < K) {
                long row = tok ? (long)tok[m0 + m] : (long)(m0 + m);
                v = A[row * lda + k0 + k];
            }
            As[k][m] = v;
        }
#pragma unroll
        for (int u = 0; u < 8; u++) {
            int i = tid + u * 128;
            int n = i >> 4, k = i & 15;
            float v = 0.0f;
            if (n0 + n < N && k0 + k < K) v = B[(long)(n0 + n) * ldb + b_off + k0 + k];
            Bs[k][n] = v;
        }
        __syncthreads();
#pragma unroll
        for (int k = 0; k < BK; k++) {
            float a[4], b[4];
#pragma unroll
            for (int i = 0; i < 4; i++) a[i] = As[k][ty * 4 + i];
#pragma unroll
            for (int j = 0; j < 4; j++) b[j] = Bs[k][tx * 4 + j];
#pragma unroll
            for (int i = 0; i < 4; i++)
#pragma unroll
                for (int j = 0; j < 4; j++) acc[i][j] = fmaf(a[i], b[j], acc[i][j]);
        }
        __syncthreads();
    }
#pragma unroll
    for (int i = 0; i < 4; i++) {
        int m = m0 + ty * 4 + i;
        if (m >= M) continue;
#pragma unroll
        for (int j = 0; j < 4; j++) {
            int n = n0 + tx * 4 + j;
            if (n >= N) continue;
            float v = acc[i][j];
            if (bias) v += bias[n];
            if (relu) v = fmaxf(v, 0.0f);
            C[(long)m * ldc + n] = v;
        }
    }
}

// ---------------- BiLSTM recurrence (byte-identical to R9, the measured best) ----------------
__global__ void __cluster_dims__(8, 1, 1) __launch_bounds__(256, 1)
lstm_kernel(const float* __restrict__ Whh_f, const float* __restrict__ Whh_b,
            const float* __restrict__ xp, float* __restrict__ h_out)
{
    __shared__ __align__(16) float hb[4][256];
    __shared__ __align__(16) unsigned long long bar[4];

    int tid = threadIdx.x;
    int dir = blockIdx.x >> 3;
    unsigned r;
    asm("mov.u32 %0, %%cluster_ctarank;" : "=r"(r));

    int h_local = tid >> 3;
    int gate = (tid >> 1) & 3;
    int half = tid & 1;
    int row = gate * 256 + (int)r * 32 + h_local;

    const unsigned long long* Wq = (const unsigned long long*)
        ((dir == 0 ? Whh_f : Whh_b) + (long)row * 256 + half * 128);
    unsigned long long wq[64];
#pragma unroll
    for (int k = 0; k < 64; k++) wq[k] = Wq[k];

    hb[0][tid] = 0.0f;
    hb[1][tid] = 0.0f;
    hb[2][tid] = 0.0f;
    hb[3][tid] = 0.0f;

    uint32_t barAddr = smem_u32(&bar[0]);
    uint32_t hbAddr  = smem_u32(&hb[0][0]);
    if (tid == 0) {
#pragma unroll
        for (int i = 0; i < 4; i++) {
            asm volatile("mbarrier.init.shared.b64 [%0], 1;" :: "r"(barAddr + i * 8) : "memory");
            asm volatile("mbarrier.arrive.expect_tx.shared.b64 _, [%0], 1024;" :: "r"(barAddr + i * 8) : "memory");
        }
    }
    __syncthreads();
    asm volatile("barrier.cluster.arrive.aligned;" ::: "memory");
    asm volatile("barrier.cluster.wait.aligned;" ::: "memory");

    uint32_t peerHb[LCL], peerBar[LCL];
#pragma unroll
    for (int pe = 0; pe < LCL; pe++) {
        asm("mapa.shared::cluster.u32 %0, %1, %2;" : "=r"(peerHb[pe])  : "r"(hbAddr),  "r"(pe));
        asm("mapa.shared::cluster.u32 %0, %1, %2;" : "=r"(peerBar[pe]) : "r"(barAddr), "r"(pe));
    }

    float c = 0.0f;
    int lane = tid & 31, gbase = lane & ~7;
    const int xcol = dir * 1024 + row;
    int t = (dir == 0) ? 0 : (T_SEQ - 1);
    int dt = (dir == 0) ? 1 : -1;
    int slot = (int)r * 32 + h_local;
    bool isProd = ((tid & 7) == 0);
    float xv = __ldg(&xp[(long)t * 2048 + xcol]);

    for (int step = 0; step < T_SEQ; step++) {
        int p = step & 3;
        if (step) {
            uint32_t mb = barAddr + p * 8;
            int par = ((step - 1) >> 2) & 1;
            asm volatile(
                "{\n\t.reg .pred P;\n"
                "WL%=:\n\t"
                "mbarrier.try_wait.parity.acquire.cta.shared::cta.b64 P, [%0], %1, 0x989680;\n\t"
                "@P bra WD%=;\n\t"
                "bra WL%=;\n"
                "WD%=:\n\t}"
                :: "r"(mb), "r"(par) : "memory");
            if (tid == 0)
                asm volatile("mbarrier.arrive.expect_tx.shared.b64 _, [%0], 1024;" :: "r"(mb) : "memory");
        }
        int tn = t + dt;
        float xnext = (step < T_SEQ - 1) ? __ldg(&xp[(long)tn * 2048 + xcol]) : 0.0f;

        const ulonglong2* h2p = (const ulonglong2*)(&hb[p][half * 128]);
        unsigned long long a0 = 0ull, a1 = 0ull, a2 = 0ull, a3 = 0ull;
#pragma unroll
        for (int k = 0; k < 16; k++) {
            ulonglong2 v0 = h2p[2 * k];
            ulonglong2 v1 = h2p[2 * k + 1];
            asm("fma.rn.f32x2 %0, %1, %2, %0;" : "+l"(a0) : "l"(wq[4 * k + 0]), "l"(v0.x));
            asm("fma.rn.f32x2 %0, %1, %2, %0;" : "+l"(a1) : "l"(wq[4 * k + 1]), "l"(v0.y));
            asm("fma.rn.f32x2 %0, %1, %2, %0;" : "+l"(a2) : "l"(wq[4 * k + 2]), "l"(v1.x));
            asm("fma.rn.f32x2 %0, %1, %2, %0;" : "+l"(a3) : "l"(wq[4 * k + 3]), "l"(v1.y));
        }
        float acc = ((__uint_as_float((unsigned)a0) + __uint_as_float((unsigned)(a0 >> 32)))
                   + (__uint_as_float((unsigned)a1) + __uint_as_float((unsigned)(a1 >> 32))))
                  + ((__uint_as_float((unsigned)a2) + __uint_as_float((unsigned)(a2 >> 32)))
                   + (__uint_as_float((unsigned)a3) + __uint_as_float((unsigned)(a3 >> 32))));
        acc += __shfl_xor_sync(0xffffffffu, acc, 1);
        float z = acc + xv;

        float zi = __shfl_sync(0xffffffffu, z, gbase + 0);
        float zf = __shfl_sync(0xffffffffu, z, gbase + 2);
        float zg = __shfl_sync(0xffffffffu, z, gbase + 4);
        float zo = __shfl_sync(0xffffffffu, z, gbase + 6);

        float ig = sigmoidf_fast(zi);
        float fg = sigmoidf_fast(zf);
        float og = sigmoidf_fast(zo);
        float gg = tanhf_fast(zg);
        c = fg * c + ig * gg;
        float hv = og * tanhf_fast(c);

        if (isProd) {
            h_out[(long)t * 512 + dir * 256 + slot] = hv;
            if (step < T_SEQ - 1) {
                int np = (step + 1) & 3;
                uint32_t doff = (uint32_t)(np * 1024 + slot * 4);
                uint32_t boff = (uint32_t)(np * 8);
#pragma unroll
                for (int pe = 0; pe < LCL; pe++) {
                    uint32_t dst = peerHb[pe] + doff;
                    uint32_t mb  = peerBar[pe] + boff;
                    asm volatile(
                        "st.async.shared::cluster.mbarrier::complete_tx::bytes.f32 [%0], %1, [%2];"
                        :: "r"(dst), "f"(hv), "r"(mb) : "memory");
                }
            }
        }
        xv = xnext;
        t = tn;
    }
    asm volatile("barrier.cluster.arrive.aligned;" ::: "memory");
    asm volatile("barrier.cluster.wait.aligned;" ::: "memory");
}

// ---------------- final 150->1 dot for attention logits ----------------
__global__ void logits_dot_kernel(const float* __restrict__ L2, const float* __restrict__ aw3,
                                  const float* __restrict__ ab3, float* __restrict__ logits) {
    int t = blockIdx.x * 8 + (threadIdx.x >> 5);
    int lane = threadIdx.x & 31;
    if (t >= T_SEQ) return;
    float s = 0.0f;
    for (int o = lane; o < A_DIM; o += 32) s += L2[(long)t * A_DIM + o] * aw3[o];
#pragma unroll
    for (int d = 16; d > 0; d >>= 1) s += __shfl_down_sync(0xffffffffu, s, d);
    if (lane == 0) logits[t] = s + ab3[0];
}

// ---------------- fused span kernel ----------------
__global__ __launch_bounds__(256) void span_kernel(
    const float* __restrict__ logits,
    const float* __restrict__ Hs, const float* __restrict__ He, const float* __restrict__ Ep,
    const float* __restrict__ sw1, const float* __restrict__ sb1,
    const float* __restrict__ sw2, const float* __restrict__ sb2,
    const float* __restrict__ sw3, const float* __restrict__ sb3,
    float* __restrict__ out)
{
    __shared__ float attn_s[32][12];
    __shared__ float x1s[32 * 153];
    __shared__ float x2s[150 * 33];
    __shared__ float swn_s[152];
    __shared__ float sb1_s[152];
    __shared__ float sb2_s[152];
    __shared__ float sw3_s[152];

    int b = blockIdx.x;
    int n = b / 128 + 1;
    int w0 = (b % 128) * 32;
    int Wn = T_SEQ + 1 - n;
    int off = (n - 1) * (T_SEQ + 1) - (n - 1) * n / 2;
    int tid = threadIdx.x;

    for (int o = tid; o < A_DIM; o += 256) {
        swn_s[o] = sw1[(long)o * G_DIM + (G_DIM - 1)];
        sb1_s[o] = sb1[o];
        sb2_s[o] = sb2[o];
        sw3_s[o] = sw3[o];
    }
    if (tid < 32) {
        int w = w0 + tid;
        if (w < Wn) {
            float m = -1e30f;
            for (int j = 0; j < n; j++) m = fmaxf(m, logits[w + j]);
            float e[10];
            float s = 0.0f;
            for (int j = 0; j < n; j++) { e[j] = __expf(logits[w + j] - m); s += e[j]; }
            float inv = __fdividef(1.0f, s);
            for (int j = 0; j < n; j++) attn_s[tid][j] = e[j] * inv;
        }
    }
    __syncthreads();

    for (int p = tid; p < 32 * A_DIM; p += 256) {
        int i = p / A_DIM, o = p - i * A_DIM;
        int w = w0 + i;
        float v = 0.0f;
        if (w < Wn) {
            float z = Hs[(long)w * A_DIM + o] + He[(long)(w + n - 1) * A_DIM + o]
                    + (float)n * swn_s[o] + sb1_s[o];
            for (int j = 0; j < n; j++)
                z = fmaf(attn_s[i][j], Ep[(long)(w + j) * A_DIM + o], z);
            v = fmaxf(z, 0.0f);
        }
        x1s[i * 153 + o] = v;
    }
    __syncthreads();

    for (int p = tid; p < A_DIM * 32; p += 256) {
        int i = p & 31;
        int o2 = p >> 5;
        const float* w2 = sw2 + (long)o2 * A_DIM;
        float z = sb2_s[o2];
#pragma unroll 5
        for (int k = 0; k < A_DIM; k++) z = fmaf(x1s[i * 153 + k], __ldg(&w2[k]), z);
        x2s[o2 * 33 + i] = fmaxf(z, 0.0f);
    }
    __syncthreads();

    {
        int i = tid >> 3;
        int cpart = tid & 7;
        float s = 0.0f;
        for (int o2 = cpart; o2 < A_DIM; o2 += 8) s = fmaf(x2s[o2 * 33 + i], sw3_s[o2], s);
        s += __shfl_down_sync(0xffffffffu, s, 4, 8);
        s += __shfl_down_sync(0xffffffffu, s, 2, 8);
        s += __shfl_down_sync(0xffffffffu, s, 1, 8);
        if (cpart == 0) {
            int w = w0 + i;
            if (w < Wn) out[off + w] = s + sb3[0];
        }
    }
}

// ---------------- launch: 3-stream fork/join (graph-capturable) ----------------
extern "C" void kernel_launch(void* const* d_in, const int* in_sizes, int n_in,
                              void* d_out, int out_size) {
    const int*   tok    = (const int*)  d_in[0];
    const float* table  = (const float*)d_in[1];
    const float* W_ih_f = (const float*)d_in[2];
    const float* W_hh_f = (const float*)d_in[3];
    const float* b_f    = (const float*)d_in[4];
    const float* W_ih_b = (const float*)d_in[5];
    const float* W_hh_b = (const float*)d_in[6];
    const float* b_b    = (const float*)d_in[7];
    const float* aw1    = (const float*)d_in[8];
    const float* ab1    = (const float*)d_in[9];
    const float* aw2    = (const float*)d_in[10];
    const float* ab2    = (const float*)d_in[11];
    const float* aw3    = (const float*)d_in[12];
    const float* ab3    = (const float*)d_in[13];
    const float* sw1    = (const float*)d_in[14];
    const float* sb1    = (const float*)d_in[15];
    const float* sw2    = (const float*)d_in[16];
    const float* sb2    = (const float*)d_in[17];
    const float* sw3    = (const float*)d_in[18];
    const float* sb3    = (const float*)d_in[19];
    float* out = (float*)d_out;

    void *p;
    float *xp, *h, *l1, *l2, *lg, *hs, *he, *ep;
    cudaGetSymbolAddress(&p, g_xp);     xp  = (float*)p;
    cudaGetSymbolAddress(&p, g_h);      h   = (float*)p;
    cudaGetSymbolAddress(&p, g_l1);     l1  = (float*)p;
    cudaGetSymbolAddress(&p, g_l2);     l2  = (float*)p;
    cudaGetSymbolAddress(&p, g_logits); lg  = (float*)p;
    cudaGetSymbolAddress(&p, g_Hs);     hs  = (float*)p;
    cudaGetSymbolAddress(&p, g_He);     he  = (float*)p;
    cudaGetSymbolAddress(&p, g_Ep);     ep  = (float*)p;

    static cudaStream_t s1 = 0, s2 = 0;
    static cudaEvent_t evA = 0, evB = 0, evC = 0, evD = 0, evE = 0;
    if (!s1) {
        cudaStreamCreateWithFlags(&s1, cudaStreamNonBlocking);
        cudaStreamCreateWithFlags(&s2, cudaStreamNonBlocking);
        cudaEventCreateWithFlags(&evA, cudaEventDisableTiming);
        cudaEventCreateWithFlags(&evB, cudaEventDisableTiming);
        cudaEventCreateWithFlags(&evC, cudaEventDisableTiming);
        cudaEventCreateWithFlags(&evD, cudaEventDisableTiming);
        cudaEventCreateWithFlags(&evE, cudaEventDisableTiming);
    }

    // fork immediately (no embed kernel: gather fused into GEMM A-loads)
    cudaEventRecord(evA, 0);
    cudaStreamWaitEvent(s1, evA, 0);
    cudaStreamWaitEvent(s2, evA, 0);
    gemm128_kernel<<<dim3(8, 32), 256, 0, 0 >>>(tok, table, W_ih_f, b_f, xp,        T_SEQ, 1024, E_DIM, E_DIM, 2048);
    gemm128_kernel<<<dim3(8, 32), 256, 0, s1>>>(tok, table, W_ih_b, b_b, xp + 1024, T_SEQ, 1024, E_DIM, E_DIM, 2048);
    gemm_kernel  <<<dim3(3, 128), 128, 0, s2>>>(tok, table, sw1, (const float*)0, ep,
                                                T_SEQ, A_DIM, E_DIM, E_DIM, G_DIM, A_DIM, 1024, 0);
    cudaEventRecord(evB, s1);
    cudaEventRecord(evE, s2);

    // lstm needs both xp halves
    cudaStreamWaitEvent(0, evB, 0);
    lstm_kernel<<<16, 256>>>(W_hh_f, W_hh_b, xp, h);
    cudaEventRecord(evC, 0);

    // fork after lstm: attention-logit chain on s1, Hs/He on main
    cudaStreamWaitEvent(s1, evC, 0);
    gemm_kernel<<<dim3(3, 128), 128, 0, s1>>>((const int*)0, h,  aw1, ab1, l1,
                                              T_SEQ, A_DIM, 512,   512,   512,   A_DIM, 0, 1);
    gemm_kernel<<<dim3(3, 128), 128, 0, s1>>>((const int*)0, l1, aw2, ab2, l2,
                                              T_SEQ, A_DIM, A_DIM, A_DIM, A_DIM, A_DIM, 0, 1);
    logits_dot_kernel<<<T_SEQ / 8, 256, 0, s1>>>(l2, aw3, ab3, lg);
    cudaEventRecord(evD, s1);

    gemm_kernel<<<dim3(3, 128), 128, 0, 0>>>((const int*)0, h, sw1, (const float*)0, hs,
                                             T_SEQ, A_DIM, 512, 512, G_DIM, A_DIM, 0,   0);
    gemm_kernel<<<dim3(3, 128), 128, 0, 0>>>((const int*)0, h, sw1, (const float*)0, he,
                                             T_SEQ, A_DIM, 512, 512, G_DIM, A_DIM, 512, 0);

    // join all branches, then span
    cudaStreamWaitEvent(0, evD, 0);
    cudaStreamWaitEvent(0, evE, 0);
    span_kernel<<<1280, 256>>>(lg, hs, he, ep, sw1, sb1, sw2, sb2, sw3, sb3, out);
}